// round 3
// baseline (speedup 1.0000x reference)
#include <cuda_runtime.h>

#define EPS 1e-6f

// Scratch accumulators (no device allocation allowed).
__device__ double g_sum;
__device__ unsigned int g_cnt;

__global__ void gsc_init()
{
    g_sum = 0.0;
    g_cnt = 0u;
}

__global__ void __launch_bounds__(256) gsc_loss(
    const float* __restrict__ pred, const float* __restrict__ gt, int B)
{
    int b = blockIdx.x * 256 + threadIdx.x;

    float pk[24], gk[24];
    if (b < B) {
        const float4* p4 = reinterpret_cast<const float4*>(pred) + (size_t)b * 6;
        const float4* g4 = reinterpret_cast<const float4*>(gt)   + (size_t)b * 6;
#pragma unroll
        for (int i = 0; i < 6; ++i) {
            float4 t = p4[i];
            pk[4*i+0] = t.x; pk[4*i+1] = t.y; pk[4*i+2] = t.z; pk[4*i+3] = t.w;
            float4 u = g4[i];
            gk[4*i+0] = u.x; gk[4*i+1] = u.y; gk[4*i+2] = u.z; gk[4*i+3] = u.w;
        }
    } else {
#pragma unroll
        for (int i = 0; i < 24; ++i) { pk[i] = 0.f; gk[i] = 0.f; }
    }

    // Stable "first 4 visible" selection, fully unrolled -> predicated SELs,
    // no dynamic register indexing, no local-memory spill.
    float px[4] = {0,0,0,0}, py[4] = {0,0,0,0};
    float gx[4] = {0,0,0,0}, gy[4] = {0,0,0,0};
    int nv = 0;
#pragma unroll
    for (int k = 0; k < 8; ++k) {
        bool vis = (pk[3*k+2] > 0.5f) && (gk[3*k+2] > 0.5f);
#pragma unroll
        for (int s = 0; s < 4; ++s) {
            if (vis && nv == s) {
                px[s] = pk[3*k+0]; py[s] = pk[3*k+1];
                gx[s] = gk[3*k+0]; gy[s] = gk[3*k+1];
            }
        }
        nv += vis ? 1 : 0;
    }
    bool valid = (b < B) && (nv >= 4);

    // ---- L_shape: cross-ratio difference ----
    float d31x = px[2]-px[0], d31y = py[2]-py[0];
    float d42x = px[3]-px[1], d42y = py[3]-py[1];
    float e31x = gx[2]-gx[0], e31y = gy[2]-gy[0];
    float e42x = gx[3]-gx[1], e42y = gy[3]-gy[1];
    float pcr = __fdividef(sqrtf(d31x*d31x + d31y*d31y),
                           sqrtf(d42x*d42x + d42y*d42y) + EPS);
    float gcr = __fdividef(sqrtf(e31x*e31x + e31y*e31y),
                           sqrtf(e42x*e42x + e42y*e42y) + EPS);
    float L_shape = fabsf(pcr - gcr);

    // ---- L_edge ----
    float v12x = px[1]-px[0], v12y = py[1]-py[0];
    float v23x = px[2]-px[1], v23y = py[2]-py[1];
    float v34x = px[3]-px[2], v34y = py[3]-py[2];
    float v41x = px[0]-px[3], v41y = py[0]-py[3];
    float l12 = sqrtf(v12x*v12x + v12y*v12y);
    float l23 = sqrtf(v23x*v23x + v23y*v23y);
    float l34 = sqrtf(v34x*v34x + v34y*v34y);
    float l41 = sqrtf(v41x*v41x + v41y*v41y);
    float par1 = __fdividef(fabsf(l12 - l34), l12 + l34 + EPS);
    float par2 = __fdividef(fabsf(l23 - l41), l23 + l41 + EPS);
    float dot1 = fabsf(__fdividef(v12x*v41x + v12y*v41y, l12*l41 + EPS));
    float dot2 = fabsf(__fdividef(v12x*v23x + v12y*v23y, l12*l23 + EPS));
    float dot3 = fabsf(__fdividef(v23x*v34x + v23y*v34y, l23*l34 + EPS));
    float dot4 = fabsf(__fdividef(v34x*v41x + v34y*v41y, l34*l41 + EPS));
    float L_edge = 0.5f*(par1 + par2) + 0.25f*(dot1 + dot2 + dot3 + dot4);

    // ---- L_pos: dist + area ratio + relative consistency ----
    float dist = 0.f;
#pragma unroll
    for (int i = 0; i < 4; ++i) {
        float dx = px[i]-gx[i], dy = py[i]-gy[i];
        dist += sqrtf(dx*dx + dy*dy);
    }
    dist *= 0.25f;

    float d41x = px[3]-px[0], d41y = py[3]-py[0];
    float parea = 0.5f * (fabsf(v12x*d31y - v12y*d31x) +
                          fabsf(d31x*d41y - d31y*d41x));
    float w12x = gx[1]-gx[0], w12y = gy[1]-gy[0];
    float e41x = gx[3]-gx[0], e41y = gy[3]-gy[0];
    float garea = 0.5f * (fabsf(w12x*e31y - w12y*e31x) +
                          fabsf(e31x*e41y - e31y*e41x));
    float area_ratio = __fdividef(fabsf(parea - garea), garea + EPS);

    float dmx = 0.25f*((px[0]-gx[0]) + (px[1]-gx[1]) + (px[2]-gx[2]) + (px[3]-gx[3]));
    float dmy = 0.25f*((py[0]-gy[0]) + (py[1]-gy[1]) + (py[2]-gy[2]) + (py[3]-gy[3]));
    float rel = 0.f;
#pragma unroll
    for (int i = 0; i < 4; ++i) {
        float dx = (px[i]-gx[i]) - dmx;
        float dy = (py[i]-gy[i]) - dmy;
        rel += sqrtf(dx*dx + dy*dy);
    }
    rel *= 0.25f;

    float L_pos = 0.4f*dist + 0.3f*area_ratio + 0.3f*rel;
    float L = 0.4f*L_shape + 0.3f*L_edge + 0.3f*L_pos;

    float contrib = valid ? L : 0.f;
    int   cnt     = valid ? 1 : 0;

    // ---- block reduction: warp shuffle -> smem -> one atomic per block ----
#pragma unroll
    for (int off = 16; off > 0; off >>= 1) {
        contrib += __shfl_down_sync(0xffffffffu, contrib, off);
        cnt     += __shfl_down_sync(0xffffffffu, cnt, off);
    }
    __shared__ float ssum[8];
    __shared__ int   scnt[8];
    int lane = threadIdx.x & 31;
    int wid  = threadIdx.x >> 5;
    if (lane == 0) { ssum[wid] = contrib; scnt[wid] = cnt; }
    __syncthreads();
    if (wid == 0) {
        float s = (lane < 8) ? ssum[lane] : 0.f;
        int   c = (lane < 8) ? scnt[lane] : 0;
#pragma unroll
        for (int off = 4; off > 0; off >>= 1) {
            s += __shfl_down_sync(0xffffffffu, s, off);
            c += __shfl_down_sync(0xffffffffu, c, off);
        }
        if (lane == 0) {
            atomicAdd(&g_sum, (double)s);
            atomicAdd(&g_cnt, (unsigned int)c);
        }
    }
}

__global__ void gsc_fin(float* out)
{
    unsigned int c = g_cnt;
    out[0] = (c > 0u) ? (float)(g_sum / (double)c) : 0.f;
}

extern "C" void kernel_launch(void* const* d_in, const int* in_sizes, int n_in,
                              void* d_out, int out_size)
{
    const float* pred = (const float*)d_in[0];
    const float* gt   = (const float*)d_in[1];
    int B = in_sizes[0] / 24;   // [B, 8, 3] float32

    gsc_init<<<1, 1>>>();
    int grid = (B + 255) / 256;
    gsc_loss<<<grid, 256>>>(pred, gt, B);
    gsc_fin<<<1, 1>>>((float*)d_out);
}